// round 5
// baseline (speedup 1.0000x reference)
#include <cuda_runtime.h>
#include <cuda_bf16.h>
#include <cstdint>
#include <cstddef>

// ---------------------------------------------------------------------------
// Problem constants
// ---------------------------------------------------------------------------
constexpr int B_  = 2;
constexpr int S_  = 2048;
constexpr int D_  = 1024;
constexpr int H_  = 16;
constexpr int DH_ = 64;
constexpr int M_  = B_ * S_;   // 4096

// ---------------------------------------------------------------------------
// Scratch: pre-split bf16 hi/lo pairs
// ---------------------------------------------------------------------------
__device__ __nv_bfloat16 g_xh[(size_t)M_ * D_], g_xl[(size_t)M_ * D_];
__device__ __nv_bfloat16 g_wh[4][(size_t)D_ * D_], g_wl[4][(size_t)D_ * D_];
__device__ __nv_bfloat16 g_qh[(size_t)M_ * D_], g_ql[(size_t)M_ * D_];
__device__ __nv_bfloat16 g_kh[(size_t)M_ * D_], g_kl[(size_t)M_ * D_];
__device__ __nv_bfloat16 g_vh[(size_t)M_ * D_], g_vl[(size_t)M_ * D_];
__device__ __nv_bfloat16 g_aoh[(size_t)M_ * D_], g_aol[(size_t)M_ * D_];

// ---------------------------------------------------------------------------
// Helpers
// ---------------------------------------------------------------------------
__device__ __forceinline__ void mma16816(float* c, const uint32_t* a, const uint32_t* b) {
    asm volatile(
        "mma.sync.aligned.m16n8k16.row.col.f32.bf16.bf16.f32 "
        "{%0,%1,%2,%3}, {%4,%5,%6,%7}, {%8,%9}, {%0,%1,%2,%3};"
        : "+f"(c[0]), "+f"(c[1]), "+f"(c[2]), "+f"(c[3])
        : "r"(a[0]), "r"(a[1]), "r"(a[2]), "r"(a[3]), "r"(b[0]), "r"(b[1]));
}

__device__ __forceinline__ void split2(float x, float y, uint32_t& hi, uint32_t& lo) {
    __nv_bfloat162 h = __floats2bfloat162_rn(x, y);
    float rx = x - __bfloat162float(h.x);
    float ry = y - __bfloat162float(h.y);
    __nv_bfloat162 l = __floats2bfloat162_rn(rx, ry);
    hi = *reinterpret_cast<uint32_t*>(&h);
    lo = *reinterpret_cast<uint32_t*>(&l);
}

__device__ __forceinline__ uint32_t smem_u32(const void* p) {
    uint32_t a;
    asm("{ .reg .u64 t; cvta.to.shared.u64 t, %1; cvt.u32.u64 %0, t; }" : "=r"(a) : "l"(p));
    return a;
}

__device__ __forceinline__ void ldsm4(uint32_t* r, uint32_t addr) {
    asm volatile("ldmatrix.sync.aligned.m8n8.x4.shared.b16 {%0,%1,%2,%3}, [%4];"
        : "=r"(r[0]), "=r"(r[1]), "=r"(r[2]), "=r"(r[3]) : "r"(addr));
}
__device__ __forceinline__ void ldsm4t(uint32_t* r, uint32_t addr) {
    asm volatile("ldmatrix.sync.aligned.m8n8.x4.trans.shared.b16 {%0,%1,%2,%3}, [%4];"
        : "=r"(r[0]), "=r"(r[1]), "=r"(r[2]), "=r"(r[3]) : "r"(addr));
}

// ---------------------------------------------------------------------------
// fp32 -> bf16 hi/lo splitter (grid-stride over float4s)
// ---------------------------------------------------------------------------
__global__ void split_fp32(const float4* __restrict__ src, uint2* __restrict__ hi,
                           uint2* __restrict__ lo, int n4)
{
    int i = blockIdx.x * blockDim.x + threadIdx.x;
    if (i >= n4) return;
    float4 f = src[i];
    uint32_t h01, l01, h23, l23;
    split2(f.x, f.y, h01, l01);
    split2(f.z, f.w, h23, l23);
    hi[i] = make_uint2(h01, h23);
    lo[i] = make_uint2(l01, l23);
}

// ---------------------------------------------------------------------------
// GEMM on pre-split bf16: out = A * W^T (3-term: AhBh + AhBl + AlBh)
// MODE 0: scatter to [B,H,S,DH] bf16 hi/lo (QKV).  MODE 1: fp32 [M,D] (final).
// Tile 128x128xK32, 8 warps, warp 64x32, fragments via lds.32 (validated).
// ---------------------------------------------------------------------------
constexpr int RS = 36;  // smem row stride in bf16 (72 B)

template <int MODE>
__global__ __launch_bounds__(256)
void gemm_bf16(const __nv_bfloat16* __restrict__ Ah_g, const __nv_bfloat16* __restrict__ Al_g,
               const __nv_bfloat16* __restrict__ Bh_g, const __nv_bfloat16* __restrict__ Bl_g,
               __nv_bfloat16* __restrict__ Oh, __nv_bfloat16* __restrict__ Ol,
               float* __restrict__ Of)
{
    __shared__ __nv_bfloat16 Ahs[128 * RS];
    __shared__ __nv_bfloat16 Als[128 * RS];
    __shared__ __nv_bfloat16 Bhs[128 * RS];
    __shared__ __nv_bfloat16 Bls[128 * RS];

    const int tid  = threadIdx.x;
    const int wid  = tid >> 5;
    const int lane = tid & 31;
    const int wm   = wid >> 2;
    const int wn   = wid & 3;
    const int bn   = blockIdx.x * 128;
    const int bm   = blockIdx.y * 128;
    const int lq   = lane >> 2;
    const int lr   = (lane & 3) << 1;

    float acc[4][4][4];
#pragma unroll
    for (int i = 0; i < 4; i++)
#pragma unroll
        for (int j = 0; j < 4; j++)
#pragma unroll
            for (int r = 0; r < 4; r++) acc[i][j][r] = 0.0f;

    // loader: row = tid>>1 (0..127), cols col0..col0+15 (2 uint4 per array)
    const int lrow = tid >> 1;
    const int col0 = (tid & 1) * 16;

    uint4 pAh[2], pAl[2], pBh[2], pBl[2];

    auto load_tile = [&](int k0) {
        const size_t ao = (size_t)(bm + lrow) * D_ + k0 + col0;
        const size_t bo = (size_t)(bn + lrow) * D_ + k0 + col0;
        pAh[0] = *(const uint4*)(Ah_g + ao);     pAh[1] = *(const uint4*)(Ah_g + ao + 8);
        pAl[0] = *(const uint4*)(Al_g + ao);     pAl[1] = *(const uint4*)(Al_g + ao + 8);
        pBh[0] = *(const uint4*)(Bh_g + bo);     pBh[1] = *(const uint4*)(Bh_g + bo + 8);
        pBl[0] = *(const uint4*)(Bl_g + bo);     pBl[1] = *(const uint4*)(Bl_g + bo + 8);
    };

    auto store_tile = [&]() {
        __nv_bfloat16* dst[4] = {Ahs, Als, Bhs, Bls};
        uint4* src[4] = {pAh, pAl, pBh, pBl};
#pragma unroll
        for (int a = 0; a < 4; ++a) {
            __nv_bfloat16* p = dst[a] + lrow * RS + col0;
            *(uint2*)(p)      = make_uint2(src[a][0].x, src[a][0].y);
            *(uint2*)(p + 4)  = make_uint2(src[a][0].z, src[a][0].w);
            *(uint2*)(p + 8)  = make_uint2(src[a][1].x, src[a][1].y);
            *(uint2*)(p + 12) = make_uint2(src[a][1].z, src[a][1].w);
        }
    };

    load_tile(0);

    for (int kt = 0; kt < 32; ++kt) {
        __syncthreads();
        store_tile();
        __syncthreads();

        if (kt < 31) load_tile((kt + 1) * 32);

#pragma unroll
        for (int ks = 0; ks < 2; ++ks) {
            const int kb = ks * 16 + lr;

            uint32_t bh[4][2], bl[4][2];
#pragma unroll
            for (int nt = 0; nt < 4; ++nt) {
                const int n = wn * 32 + nt * 8 + lq;
                bh[nt][0] = *(const uint32_t*)&Bhs[n * RS + kb];
                bh[nt][1] = *(const uint32_t*)&Bhs[n * RS + kb + 8];
                bl[nt][0] = *(const uint32_t*)&Bls[n * RS + kb];
                bl[nt][1] = *(const uint32_t*)&Bls[n * RS + kb + 8];
            }

#pragma unroll
            for (int mt = 0; mt < 4; ++mt) {
                const int r = wm * 64 + mt * 16 + lq;
                uint32_t ah[4], al[4];
                ah[0] = *(const uint32_t*)&Ahs[r * RS + kb];
                ah[1] = *(const uint32_t*)&Ahs[(r + 8) * RS + kb];
                ah[2] = *(const uint32_t*)&Ahs[r * RS + kb + 8];
                ah[3] = *(const uint32_t*)&Ahs[(r + 8) * RS + kb + 8];
                al[0] = *(const uint32_t*)&Als[r * RS + kb];
                al[1] = *(const uint32_t*)&Als[(r + 8) * RS + kb];
                al[2] = *(const uint32_t*)&Als[r * RS + kb + 8];
                al[3] = *(const uint32_t*)&Als[(r + 8) * RS + kb + 8];
#pragma unroll
                for (int nt = 0; nt < 4; ++nt) {
                    mma16816(acc[mt][nt], ah, bh[nt]);
                    mma16816(acc[mt][nt], ah, bl[nt]);
                    mma16816(acc[mt][nt], al, bh[nt]);
                }
            }
        }
    }

#pragma unroll
    for (int mt = 0; mt < 4; ++mt) {
#pragma unroll
        for (int nt = 0; nt < 4; ++nt) {
            const int n  = bn + wn * 32 + nt * 8 + lr;
            const int m0 = bm + wm * 64 + mt * 16 + lq;
#pragma unroll
            for (int half = 0; half < 2; ++half) {
                const int m = m0 + half * 8;
                const float v0 = acc[mt][nt][half * 2];
                const float v1 = acc[mt][nt][half * 2 + 1];
                if (MODE == 0) {
                    const int b_ = m >> 11;
                    const int s_ = m & 2047;
                    const int h_ = n >> 6;
                    const int d_ = n & 63;
                    const size_t off = (((size_t)(b_ * H_ + h_) * S_ + s_) << 6) + d_;
                    uint32_t hh, ll;
                    split2(v0, v1, hh, ll);
                    *(uint32_t*)&Oh[off] = hh;
                    *(uint32_t*)&Ol[off] = ll;
                } else {
                    *(float2*)&Of[(size_t)m * D_ + n] = make_float2(v0, v1);
                }
            }
        }
    }
}

// ---------------------------------------------------------------------------
// Flash attention on pre-split bf16 Q/K/V (causal).
// Block = 128 q rows x (head, batch). 8 warps x 16 rows.
// K,V tiles natural [seq][dh] in smem (uint4 copies); K frags via ldmatrix.x4,
// V frags via ldmatrix.x4.trans. Softmax fp32; P split in-register.
// Output written pre-split (hi/lo bf16) for the final GEMM.
// ---------------------------------------------------------------------------
constexpr int ARS = 72;  // attn smem row stride in bf16 (144 B, 16B-aligned rows)

__global__ __launch_bounds__(256)
void attn_mma(const __nv_bfloat16* __restrict__ Qh_g, const __nv_bfloat16* __restrict__ Ql_g,
              const __nv_bfloat16* __restrict__ Kh_g, const __nv_bfloat16* __restrict__ Kl_g,
              const __nv_bfloat16* __restrict__ Vh_g, const __nv_bfloat16* __restrict__ Vl_g,
              __nv_bfloat16* __restrict__ AOh, __nv_bfloat16* __restrict__ AOl)
{
    __shared__ __nv_bfloat16 Khs[64 * ARS];
    __shared__ __nv_bfloat16 Kls[64 * ARS];
    __shared__ __nv_bfloat16 Vhs[64 * ARS];
    __shared__ __nv_bfloat16 Vls[64 * ARS];

    const int tid  = threadIdx.x;
    const int wid  = tid >> 5;
    const int lane = tid & 31;
    const int lq   = lane >> 2;
    const int c2   = (lane & 3) << 1;

    const int qt = (int)gridDim.x - 1 - (int)blockIdx.x;   // heavy tiles first
    const int q0 = qt * 128;
    const int h  = blockIdx.y;
    const int b  = blockIdx.z;
    const size_t base = (size_t)(b * H_ + h) * S_ * DH_;
    const int wrow = wid * 16;

    // ldmatrix per-lane address components
    const uint32_t kh_u = smem_u32(Khs), kl_u = smem_u32(Kls);
    const uint32_t vh_u = smem_u32(Vhs), vl_u = smem_u32(Vls);
    const int kn_off = (lane & 7) + ((lane & 16) ? 8 : 0);  // K: row (n) offset
    const int kk_off = (lane & 8);                          // K: col (k) offset
    const int vr_off = lane & 15;                           // V: row (k=seq) offset
    const int vc_off = (lane & 16) ? 8 : 0;                 // V: col (n=dh) offset

    // ---- Q fragments from pre-split gmem ----
    uint32_t qh[4][4], ql[4][4];
    {
        const __nv_bfloat16* qhp = Qh_g + base + (size_t)(q0 + wrow + lq) * DH_;
        const __nv_bfloat16* qlp = Ql_g + base + (size_t)(q0 + wrow + lq) * DH_;
#pragma unroll
        for (int kt = 0; kt < 4; ++kt) {
            const int c = kt * 16 + c2;
            qh[kt][0] = *(const uint32_t*)(qhp + c);
            qh[kt][1] = *(const uint32_t*)(qhp + 8 * DH_ + c);
            qh[kt][2] = *(const uint32_t*)(qhp + c + 8);
            qh[kt][3] = *(const uint32_t*)(qhp + 8 * DH_ + c + 8);
            ql[kt][0] = *(const uint32_t*)(qlp + c);
            ql[kt][1] = *(const uint32_t*)(qlp + 8 * DH_ + c);
            ql[kt][2] = *(const uint32_t*)(qlp + c + 8);
            ql[kt][3] = *(const uint32_t*)(qlp + 8 * DH_ + c + 8);
        }
    }

    float oacc[8][4];
#pragma unroll
    for (int nt = 0; nt < 8; ++nt)
#pragma unroll
        for (int r = 0; r < 4; ++r) oacc[nt][r] = 0.0f;

    float m0 = -1e30f, m1 = -1e30f, l0 = 0.0f, l1 = 0.0f;

    constexpr float scale = 0.125f;
    const int r0g = q0 + wrow + lq;
    const int r1g = r0g + 8;
    const int rmaxWarp = q0 + wrow + 15;

    for (int k0 = 0; k0 < q0 + 128; k0 += 64) {
        __syncthreads();

        // ---- tile copy: gmem bf16 -> smem (uint4 = 8 bf16) ----
#pragma unroll
        for (int it = 0; it < 2; ++it) {
            const int idx = tid + it * 256;     // 0..511
            const int r   = idx >> 3;           // seq 0..63
            const int c8  = (idx & 7) << 3;     // dh 0..56
            const size_t go = base + (size_t)(k0 + r) * DH_ + c8;
            const int so = r * ARS + c8;
            *(uint4*)&Khs[so] = *(const uint4*)(Kh_g + go);
            *(uint4*)&Kls[so] = *(const uint4*)(Kl_g + go);
            *(uint4*)&Vhs[so] = *(const uint4*)(Vh_g + go);
            *(uint4*)&Vls[so] = *(const uint4*)(Vl_g + go);
        }
        __syncthreads();

        if (k0 > rmaxWarp) continue;

        // ---- S = Q K^T (3-term split), K frags via ldmatrix.x4 ----
        float sc[8][4];
#pragma unroll
        for (int nt = 0; nt < 8; ++nt)
#pragma unroll
            for (int r = 0; r < 4; ++r) sc[nt][r] = 0.0f;

#pragma unroll
        for (int kt = 0; kt < 4; ++kt) {
#pragma unroll
            for (int nt2 = 0; nt2 < 4; ++nt2) {
                const uint32_t boff =
                    (uint32_t)(((nt2 * 16 + kn_off) * ARS + kt * 16 + kk_off) * 2);
                uint32_t kh4[4], kl4[4];
                ldsm4(kh4, kh_u + boff);
                ldsm4(kl4, kl_u + boff);
                const int nt = nt2 * 2;
                mma16816(sc[nt],     qh[kt], kh4);
                mma16816(sc[nt],     qh[kt], kl4);
                mma16816(sc[nt],     ql[kt], kh4);
                mma16816(sc[nt + 1], qh[kt], kh4 + 2);
                mma16816(sc[nt + 1], qh[kt], kl4 + 2);
                mma16816(sc[nt + 1], ql[kt], kh4 + 2);
            }
        }

        // ---- scale + causal mask ----
        const bool needMask = (k0 + 64 > q0 + wrow);
#pragma unroll
        for (int nt = 0; nt < 8; ++nt) {
            const int c0g = k0 + nt * 8 + c2;
            sc[nt][0] *= scale; sc[nt][1] *= scale;
            sc[nt][2] *= scale; sc[nt][3] *= scale;
            if (needMask) {
                if (c0g     > r0g) sc[nt][0] = -1e30f;
                if (c0g + 1 > r0g) sc[nt][1] = -1e30f;
                if (c0g     > r1g) sc[nt][2] = -1e30f;
                if (c0g + 1 > r1g) sc[nt][3] = -1e30f;
            }
        }

        // ---- online softmax ----
        float mx0 = -1e30f, mx1 = -1e30f;
#pragma unroll
        for (int nt = 0; nt < 8; ++nt) {
            mx0 = fmaxf(mx0, fmaxf(sc[nt][0], sc[nt][1]));
            mx1 = fmaxf(mx1, fmaxf(sc[nt][2], sc[nt][3]));
        }
        mx0 = fmaxf(mx0, __shfl_xor_sync(0xffffffffu, mx0, 1));
        mx0 = fmaxf(mx0, __shfl_xor_sync(0xffffffffu, mx0, 2));
        mx1 = fmaxf(mx1, __shfl_xor_sync(0xffffffffu, mx1, 1));
        mx1 = fmaxf(mx1, __shfl_xor_sync(0xffffffffu, mx1, 2));

        const float mn0 = fmaxf(m0, mx0);
        const float mn1 = fmaxf(m1, mx1);
        const float corr0 = __expf(m0 - mn0);
        const float corr1 = __expf(m1 - mn1);
        m0 = mn0; m1 = mn1;

        float rs0 = 0.0f, rs1 = 0.0f;
#pragma unroll
        for (int nt = 0; nt < 8; ++nt) {
            float p0 = __expf(sc[nt][0] - mn0);
            float p1 = __expf(sc[nt][1] - mn0);
            float p2 = __expf(sc[nt][2] - mn1);
            float p3 = __expf(sc[nt][3] - mn1);
            sc[nt][0] = p0; sc[nt][1] = p1; sc[nt][2] = p2; sc[nt][3] = p3;
            rs0 += p0 + p1;
            rs1 += p2 + p3;
        }
        rs0 += __shfl_xor_sync(0xffffffffu, rs0, 1);
        rs0 += __shfl_xor_sync(0xffffffffu, rs0, 2);
        rs1 += __shfl_xor_sync(0xffffffffu, rs1, 1);
        rs1 += __shfl_xor_sync(0xffffffffu, rs1, 2);
        l0 = l0 * corr0 + rs0;
        l1 = l1 * corr1 + rs1;

#pragma unroll
        for (int nt = 0; nt < 8; ++nt) {
            oacc[nt][0] *= corr0; oacc[nt][1] *= corr0;
            oacc[nt][2] *= corr1; oacc[nt][3] *= corr1;
        }

        // ---- pack P into A fragments (split hi/lo, in-register) ----
        uint32_t ph[4][4], pl[4][4];
#pragma unroll
        for (int kt = 0; kt < 4; ++kt) {
            const int t0 = 2 * kt, t1 = 2 * kt + 1;
            split2(sc[t0][0], sc[t0][1], ph[kt][0], pl[kt][0]);
            split2(sc[t0][2], sc[t0][3], ph[kt][1], pl[kt][1]);
            split2(sc[t1][0], sc[t1][1], ph[kt][2], pl[kt][2]);
            split2(sc[t1][2], sc[t1][3], ph[kt][3], pl[kt][3]);
        }

        // ---- O += P V (3-term split), V frags via ldmatrix.x4.trans ----
#pragma unroll
        for (int kt = 0; kt < 4; ++kt) {
#pragma unroll
            for (int nt2 = 0; nt2 < 4; ++nt2) {
                const uint32_t boff =
                    (uint32_t)(((kt * 16 + vr_off) * ARS + nt2 * 16 + vc_off) * 2);
                uint32_t vh4[4], vl4[4];
                ldsm4t(vh4, vh_u + boff);
                ldsm4t(vl4, vl_u + boff);
                const int nt = nt2 * 2;
                mma16816(oacc[nt],     ph[kt], vh4);
                mma16816(oacc[nt],     ph[kt], vl4);
                mma16816(oacc[nt],     pl[kt], vh4);
                mma16816(oacc[nt + 1], ph[kt], vh4 + 2);
                mma16816(oacc[nt + 1], ph[kt], vl4 + 2);
                mma16816(oacc[nt + 1], pl[kt], vh4 + 2);
            }
        }
    }

    // ---- epilogue: normalize, split, write pre-split [B,S,D] ----
    const float inv0 = 1.0f / l0;
    const float inv1 = 1.0f / l1;
#pragma unroll
    for (int nt = 0; nt < 8; ++nt) {
        const int d = h * DH_ + nt * 8 + c2;
        uint32_t hh, ll;
        split2(oacc[nt][0] * inv0, oacc[nt][1] * inv0, hh, ll);
        *(uint32_t*)&AOh[(size_t)(b * S_ + r0g) * D_ + d] = hh;
        *(uint32_t*)&AOl[(size_t)(b * S_ + r0g) * D_ + d] = ll;
        split2(oacc[nt][2] * inv1, oacc[nt][3] * inv1, hh, ll);
        *(uint32_t*)&AOh[(size_t)(b * S_ + r1g) * D_ + d] = hh;
        *(uint32_t*)&AOl[(size_t)(b * S_ + r1g) * D_ + d] = ll;
    }
}

// ---------------------------------------------------------------------------
// Launch
// ---------------------------------------------------------------------------
extern "C" void kernel_launch(void* const* d_in, const int* in_sizes, int n_in,
                              void* d_out, int out_size)
{
    const float* x  = (const float*)d_in[0];
    const float* w[4] = {(const float*)d_in[1], (const float*)d_in[2],
                         (const float*)d_in[3], (const float*)d_in[4]};
    float* out = (float*)d_out;

    void *pxh, *pxl, *pwh, *pwl, *pqh, *pql, *pkh, *pkl, *pvh, *pvl, *paoh, *paol;
    cudaGetSymbolAddress(&pxh, g_xh);   cudaGetSymbolAddress(&pxl, g_xl);
    cudaGetSymbolAddress(&pwh, g_wh);   cudaGetSymbolAddress(&pwl, g_wl);
    cudaGetSymbolAddress(&pqh, g_qh);   cudaGetSymbolAddress(&pql, g_ql);
    cudaGetSymbolAddress(&pkh, g_kh);   cudaGetSymbolAddress(&pkl, g_kl);
    cudaGetSymbolAddress(&pvh, g_vh);   cudaGetSymbolAddress(&pvl, g_vl);
    cudaGetSymbolAddress(&paoh, g_aoh); cudaGetSymbolAddress(&paol, g_aol);

    __nv_bfloat16* xh = (__nv_bfloat16*)pxh;  __nv_bfloat16* xl = (__nv_bfloat16*)pxl;
    __nv_bfloat16* wh = (__nv_bfloat16*)pwh;  __nv_bfloat16* wl = (__nv_bfloat16*)pwl;
    __nv_bfloat16* qh = (__nv_bfloat16*)pqh;  __nv_bfloat16* ql = (__nv_bfloat16*)pql;
    __nv_bfloat16* kh = (__nv_bfloat16*)pkh;  __nv_bfloat16* kl = (__nv_bfloat16*)pkl;
    __nv_bfloat16* vh = (__nv_bfloat16*)pvh;  __nv_bfloat16* vl = (__nv_bfloat16*)pvl;
    __nv_bfloat16* aoh = (__nv_bfloat16*)paoh; __nv_bfloat16* aol = (__nv_bfloat16*)paol;

    // Pre-split x and weights
    {
        const int n4x = M_ * D_ / 4;
        split_fp32<<<(n4x + 255) / 256, 256>>>((const float4*)x, (uint2*)xh, (uint2*)xl, n4x);
        const int n4w = D_ * D_ / 4;
        for (int i = 0; i < 4; ++i)
            split_fp32<<<(n4w + 255) / 256, 256>>>((const float4*)w[i],
                (uint2*)(wh + (size_t)i * D_ * D_), (uint2*)(wl + (size_t)i * D_ * D_), n4w);
    }

    dim3 gemm_grid(D_ / 128, M_ / 128);   // (8, 32)
    gemm_bf16<0><<<gemm_grid, 256>>>(xh, xl, wh + 0 * (size_t)D_ * D_, wl + 0 * (size_t)D_ * D_, qh, ql, nullptr);
    gemm_bf16<0><<<gemm_grid, 256>>>(xh, xl, wh + 1 * (size_t)D_ * D_, wl + 1 * (size_t)D_ * D_, kh, kl, nullptr);
    gemm_bf16<0><<<gemm_grid, 256>>>(xh, xl, wh + 2 * (size_t)D_ * D_, wl + 2 * (size_t)D_ * D_, vh, vl, nullptr);

    dim3 attn_grid(S_ / 128, H_, B_);     // (16, 16, 2)
    attn_mma<<<attn_grid, 256>>>(qh, ql, kh, kl, vh, vl, aoh, aol);

    gemm_bf16<1><<<gemm_grid, 256>>>(aoh, aol, wh + 3 * (size_t)D_ * D_, wl + 3 * (size_t)D_ * D_, nullptr, nullptr, out);
}

// round 7
// speedup vs baseline: 1.3006x; 1.3006x over previous
#include <cuda_runtime.h>
#include <cuda_bf16.h>
#include <cstdint>
#include <cstddef>

// ---------------------------------------------------------------------------
// Problem constants
// ---------------------------------------------------------------------------
constexpr int B_  = 2;
constexpr int S_  = 2048;
constexpr int D_  = 1024;
constexpr int H_  = 16;
constexpr int DH_ = 64;
constexpr int M_  = B_ * S_;   // 4096

// ---------------------------------------------------------------------------
// Scratch: pre-split bf16 hi/lo pairs (16B-aligned for cp.async)
// ---------------------------------------------------------------------------
__device__ __align__(256) __nv_bfloat16 g_xh[(size_t)M_ * D_], g_xl[(size_t)M_ * D_];
__device__ __align__(256) __nv_bfloat16 g_wh[4][(size_t)D_ * D_], g_wl[4][(size_t)D_ * D_];
__device__ __align__(256) __nv_bfloat16 g_qkvh[3][(size_t)M_ * D_], g_qkvl[3][(size_t)M_ * D_];
__device__ __align__(256) __nv_bfloat16 g_aoh[(size_t)M_ * D_], g_aol[(size_t)M_ * D_];

// ---------------------------------------------------------------------------
// Helpers
// ---------------------------------------------------------------------------
__device__ __forceinline__ void mma16816(float* c, const uint32_t* a, const uint32_t* b) {
    asm volatile(
        "mma.sync.aligned.m16n8k16.row.col.f32.bf16.bf16.f32 "
        "{%0,%1,%2,%3}, {%4,%5,%6,%7}, {%8,%9}, {%0,%1,%2,%3};"
        : "+f"(c[0]), "+f"(c[1]), "+f"(c[2]), "+f"(c[3])
        : "r"(a[0]), "r"(a[1]), "r"(a[2]), "r"(a[3]), "r"(b[0]), "r"(b[1]));
}

__device__ __forceinline__ void split2(float x, float y, uint32_t& hi, uint32_t& lo) {
    __nv_bfloat162 h = __floats2bfloat162_rn(x, y);
    float rx = x - __bfloat162float(h.x);
    float ry = y - __bfloat162float(h.y);
    __nv_bfloat162 l = __floats2bfloat162_rn(rx, ry);
    hi = *reinterpret_cast<uint32_t*>(&h);
    lo = *reinterpret_cast<uint32_t*>(&l);
}

__device__ __forceinline__ uint32_t smem_u32(const void* p) {
    uint32_t a;
    asm("{ .reg .u64 t; cvta.to.shared.u64 t, %1; cvt.u32.u64 %0, t; }" : "=r"(a) : "l"(p));
    return a;
}

__device__ __forceinline__ void ldsm4(uint32_t* r, uint32_t addr) {
    asm volatile("ldmatrix.sync.aligned.m8n8.x4.shared.b16 {%0,%1,%2,%3}, [%4];"
        : "=r"(r[0]), "=r"(r[1]), "=r"(r[2]), "=r"(r[3]) : "r"(addr));
}
__device__ __forceinline__ void ldsm4t(uint32_t* r, uint32_t addr) {
    asm volatile("ldmatrix.sync.aligned.m8n8.x4.trans.shared.b16 {%0,%1,%2,%3}, [%4];"
        : "=r"(r[0]), "=r"(r[1]), "=r"(r[2]), "=r"(r[3]) : "r"(addr));
}

__device__ __forceinline__ void cp16(uint32_t saddr, const void* g) {
    asm volatile("cp.async.cg.shared.global [%0], [%1], 16;" :: "r"(saddr), "l"(g));
}
__device__ __forceinline__ void cp_commit() { asm volatile("cp.async.commit_group;"); }
template <int N> __device__ __forceinline__ void cp_wait() {
    asm volatile("cp.async.wait_group %0;" :: "n"(N));
}

// ---------------------------------------------------------------------------
// fp32 -> bf16 hi/lo splitter
// ---------------------------------------------------------------------------
__global__ void split_fp32(const float4* __restrict__ src, uint2* __restrict__ hi,
                           uint2* __restrict__ lo, int n4)
{
    int i = blockIdx.x * blockDim.x + threadIdx.x;
    if (i >= n4) return;
    float4 f = src[i];
    uint32_t h01, l01, h23, l23;
    split2(f.x, f.y, h01, l01);
    split2(f.z, f.w, h23, l23);
    hi[i] = make_uint2(h01, h23);
    lo[i] = make_uint2(l01, l23);
}

// ---------------------------------------------------------------------------
// GEMM on pre-split bf16 with cp.async 2-stage pipeline.
// out = A * W^T, 3-term split. Tile 128x128xK32, 8 warps, warp 64x32.
// MODE 0: fused QKV (blockIdx.x>>3 selects weight/output), scatter bf16 hi/lo.
// MODE 1: single weight, fp32 row-major output.
// Dyn smem: [stage 2][array 4: Ah,Al,Bh,Bl][128*RS] bf16, RS=40 (80B rows).
// ---------------------------------------------------------------------------
constexpr int RS = 40;                                   // 32 data + 8 pad
constexpr int GEMM_TILE_BF16 = 128 * RS;
constexpr int GEMM_SMEM = 2 * 4 * GEMM_TILE_BF16 * 2;    // 81920 B

template <int MODE>
__global__ __launch_bounds__(256, 2)
void gemm_bf16(const __nv_bfloat16* __restrict__ Ah_g, const __nv_bfloat16* __restrict__ Al_g,
               const __nv_bfloat16* __restrict__ Wh0, const __nv_bfloat16* __restrict__ Wl0,
               __nv_bfloat16* __restrict__ Oh0, __nv_bfloat16* __restrict__ Ol0,
               float* __restrict__ Of)
{
    extern __shared__ __nv_bfloat16 smem[];

    const int tid  = threadIdx.x;
    const int wid  = tid >> 5;
    const int lane = tid & 31;
    const int wm   = wid >> 2;
    const int wn   = wid & 3;
    const int lq   = lane >> 2;
    const int lr   = (lane & 3) << 1;

    int wsel, bn;
    if (MODE == 0) { wsel = blockIdx.x >> 3; bn = (blockIdx.x & 7) * 128; }
    else           { wsel = 0;               bn = blockIdx.x * 128; }
    const int bm = blockIdx.y * 128;

    const __nv_bfloat16* Bh_g = Wh0 + (size_t)wsel * D_ * D_;
    const __nv_bfloat16* Bl_g = Wl0 + (size_t)wsel * D_ * D_;

    const uint32_t sbase = smem_u32(smem);

    // copy mapping: i -> array i>>1; c=(i&1)*256+tid; row=c>>2; col16=c&3
    auto issue = [&](int k0, int s) {
#pragma unroll
        for (int i = 0; i < 8; ++i) {
            const int a    = i >> 1;
            const int c    = (i & 1) * 256 + tid;
            const int row  = c >> 2;
            const int c16  = c & 3;
            const size_t go = (size_t)((a < 2 ? bm : bn) + row) * D_ + k0 + c16 * 8;
            const __nv_bfloat16* g =
                (a == 0) ? Ah_g + go : (a == 1) ? Al_g + go :
                (a == 2) ? Bh_g + go : Bl_g + go;
            const uint32_t sa = sbase + (uint32_t)(((s * 4 + a) * GEMM_TILE_BF16
                                 + row * RS) * 2 + c16 * 16);
            cp16(sa, g);
        }
        cp_commit();
    };

    float acc[4][4][4];
#pragma unroll
    for (int i = 0; i < 4; i++)
#pragma unroll
        for (int j = 0; j < 4; j++)
#pragma unroll
            for (int r = 0; r < 4; r++) acc[i][j][r] = 0.0f;

    issue(0, 0);

    for (int kt = 0; kt < 32; ++kt) {
        const int s = kt & 1;
        if (kt < 31) { issue((kt + 1) * 32, s ^ 1); cp_wait<1>(); }
        else         { cp_wait<0>(); }
        __syncthreads();

        const __nv_bfloat16* Ahs = smem + (s * 4 + 0) * GEMM_TILE_BF16;
        const __nv_bfloat16* Als = smem + (s * 4 + 1) * GEMM_TILE_BF16;
        const __nv_bfloat16* Bhs = smem + (s * 4 + 2) * GEMM_TILE_BF16;
        const __nv_bfloat16* Bls = smem + (s * 4 + 3) * GEMM_TILE_BF16;

#pragma unroll
        for (int ks = 0; ks < 2; ++ks) {
            const int kb = ks * 16 + lr;

            uint32_t bh[4][2], bl[4][2];
#pragma unroll
            for (int nt = 0; nt < 4; ++nt) {
                const int n = wn * 32 + nt * 8 + lq;
                bh[nt][0] = *(const uint32_t*)&Bhs[n * RS + kb];
                bh[nt][1] = *(const uint32_t*)&Bhs[n * RS + kb + 8];
                bl[nt][0] = *(const uint32_t*)&Bls[n * RS + kb];
                bl[nt][1] = *(const uint32_t*)&Bls[n * RS + kb + 8];
            }

#pragma unroll
            for (int mt = 0; mt < 4; ++mt) {
                const int r = wm * 64 + mt * 16 + lq;
                uint32_t ah[4], al[4];
                ah[0] = *(const uint32_t*)&Ahs[r * RS + kb];
                ah[1] = *(const uint32_t*)&Ahs[(r + 8) * RS + kb];
                ah[2] = *(const uint32_t*)&Ahs[r * RS + kb + 8];
                ah[3] = *(const uint32_t*)&Ahs[(r + 8) * RS + kb + 8];
                al[0] = *(const uint32_t*)&Als[r * RS + kb];
                al[1] = *(const uint32_t*)&Als[(r + 8) * RS + kb];
                al[2] = *(const uint32_t*)&Als[r * RS + kb + 8];
                al[3] = *(const uint32_t*)&Als[(r + 8) * RS + kb + 8];
#pragma unroll
                for (int nt = 0; nt < 4; ++nt) {
                    mma16816(acc[mt][nt], ah, bh[nt]);
                    mma16816(acc[mt][nt], ah, bl[nt]);
                    mma16816(acc[mt][nt], al, bh[nt]);
                }
            }
        }
        __syncthreads();
    }

    __nv_bfloat16* Oh = (MODE == 0) ? Oh0 + (size_t)wsel * M_ * D_ : nullptr;
    __nv_bfloat16* Ol = (MODE == 0) ? Ol0 + (size_t)wsel * M_ * D_ : nullptr;

#pragma unroll
    for (int mt = 0; mt < 4; ++mt) {
#pragma unroll
        for (int nt = 0; nt < 4; ++nt) {
            const int n  = bn + wn * 32 + nt * 8 + lr;
            const int m0 = bm + wm * 64 + mt * 16 + lq;
#pragma unroll
            for (int half = 0; half < 2; ++half) {
                const int m = m0 + half * 8;
                const float v0 = acc[mt][nt][half * 2];
                const float v1 = acc[mt][nt][half * 2 + 1];
                if (MODE == 0) {
                    const int b_ = m >> 11;
                    const int s_ = m & 2047;
                    const int h_ = n >> 6;
                    const int d_ = n & 63;
                    const size_t off = (((size_t)(b_ * H_ + h_) * S_ + s_) << 6) + d_;
                    uint32_t hh, ll;
                    split2(v0, v1, hh, ll);
                    *(uint32_t*)&Oh[off] = hh;
                    *(uint32_t*)&Ol[off] = ll;
                } else {
                    *(float2*)&Of[(size_t)m * D_ + n] = make_float2(v0, v1);
                }
            }
        }
    }
}

// ---------------------------------------------------------------------------
// Flash attention on pre-split bf16 with cp.async 2-stage K/V pipeline.
// Block = 128 q rows x (head, batch). 8 warps x 16 rows.
// smem: [stage 2][array 4: Kh,Kl,Vh,Vl][64*ARS], ARS=72 (144B rows — the
// Round-5-validated geometry for 64-wide tiles). 73728 B dynamic.
// ---------------------------------------------------------------------------
constexpr int ARS = 72;                       // 64 data + 8 pad
constexpr int ATT_TILE_BF16 = 64 * ARS;       // 4608
constexpr int ATT_SMEM = 2 * 4 * ATT_TILE_BF16 * 2;   // 73728 B

__global__ __launch_bounds__(256)
void attn_mma(const __nv_bfloat16* __restrict__ Qh_g, const __nv_bfloat16* __restrict__ Ql_g,
              const __nv_bfloat16* __restrict__ Kh_g, const __nv_bfloat16* __restrict__ Kl_g,
              const __nv_bfloat16* __restrict__ Vh_g, const __nv_bfloat16* __restrict__ Vl_g,
              __nv_bfloat16* __restrict__ AOh, __nv_bfloat16* __restrict__ AOl)
{
    extern __shared__ __nv_bfloat16 asmem[];

    const int tid  = threadIdx.x;
    const int wid  = tid >> 5;
    const int lane = tid & 31;
    const int lq   = lane >> 2;
    const int c2   = (lane & 3) << 1;

    const int qt = (int)gridDim.x - 1 - (int)blockIdx.x;   // heavy tiles first
    const int q0 = qt * 128;
    const int h  = blockIdx.y;
    const int b  = blockIdx.z;
    const size_t base = (size_t)(b * H_ + h) * S_ * DH_;
    const int wrow = wid * 16;

    const uint32_t sbase = smem_u32(asmem);
    const int kn_off = (lane & 7) + ((lane & 16) ? 8 : 0);
    const int kk_off = (lane & 8);
    const int vr_off = lane & 15;
    const int vc_off = (lane & 16) ? 8 : 0;

    // copy mapping: per array 512 cp16s; idx = tid + it*256; row=idx>>3 (0..63),
    // c16=idx&7 (col = c16*8, full 64-wide row covered).
    auto issue = [&](int k0, int s) {
#pragma unroll
        for (int it = 0; it < 2; ++it) {
            const int idx = tid + it * 256;
            const int row = idx >> 3;
            const int c16 = idx & 7;
            const size_t go = base + (size_t)(k0 + row) * DH_ + c16 * 8;
            const uint32_t so = (uint32_t)(row * ARS * 2 + c16 * 16);
#pragma unroll
            for (int a = 0; a < 4; ++a) {
                const __nv_bfloat16* g =
                    (a == 0) ? Kh_g + go : (a == 1) ? Kl_g + go :
                    (a == 2) ? Vh_g + go : Vl_g + go;
                cp16(sbase + (uint32_t)((s * 4 + a) * ATT_TILE_BF16 * 2) + so, g);
            }
        }
        cp_commit();
    };

    // ---- Q fragments ----
    uint32_t qh[4][4], ql[4][4];
    {
        const __nv_bfloat16* qhp = Qh_g + base + (size_t)(q0 + wrow + lq) * DH_;
        const __nv_bfloat16* qlp = Ql_g + base + (size_t)(q0 + wrow + lq) * DH_;
#pragma unroll
        for (int kt = 0; kt < 4; ++kt) {
            const int c = kt * 16 + c2;
            qh[kt][0] = *(const uint32_t*)(qhp + c);
            qh[kt][1] = *(const uint32_t*)(qhp + 8 * DH_ + c);
            qh[kt][2] = *(const uint32_t*)(qhp + c + 8);
            qh[kt][3] = *(const uint32_t*)(qhp + 8 * DH_ + c + 8);
            ql[kt][0] = *(const uint32_t*)(qlp + c);
            ql[kt][1] = *(const uint32_t*)(qlp + 8 * DH_ + c);
            ql[kt][2] = *(const uint32_t*)(qlp + c + 8);
            ql[kt][3] = *(const uint32_t*)(qlp + 8 * DH_ + c + 8);
        }
    }

    float oacc[8][4];
#pragma unroll
    for (int nt = 0; nt < 8; ++nt)
#pragma unroll
        for (int r = 0; r < 4; ++r) oacc[nt][r] = 0.0f;

    float m0 = -1e30f, m1 = -1e30f, l0 = 0.0f, l1 = 0.0f;

    constexpr float scale = 0.125f;
    const int r0g = q0 + wrow + lq;
    const int r1g = r0g + 8;
    const int rmaxWarp = q0 + wrow + 15;
    const int ntiles = q0 / 64 + 2;

    issue(0, 0);

    for (int t = 0; t < ntiles; ++t) {
        const int s  = t & 1;
        const int k0 = t * 64;
        if (t + 1 < ntiles) { issue((t + 1) * 64, s ^ 1); cp_wait<1>(); }
        else                { cp_wait<0>(); }
        __syncthreads();

        if (k0 <= rmaxWarp) {
            const uint32_t khu = sbase + (uint32_t)((s * 4 + 0) * ATT_TILE_BF16 * 2);
            const uint32_t klu = sbase + (uint32_t)((s * 4 + 1) * ATT_TILE_BF16 * 2);
            const uint32_t vhu = sbase + (uint32_t)((s * 4 + 2) * ATT_TILE_BF16 * 2);
            const uint32_t vlu = sbase + (uint32_t)((s * 4 + 3) * ATT_TILE_BF16 * 2);

            // ---- S = Q K^T ----
            float sc[8][4];
#pragma unroll
            for (int nt = 0; nt < 8; ++nt)
#pragma unroll
                for (int r = 0; r < 4; ++r) sc[nt][r] = 0.0f;

#pragma unroll
            for (int kt = 0; kt < 4; ++kt) {
#pragma unroll
                for (int nt2 = 0; nt2 < 4; ++nt2) {
                    const uint32_t boff =
                        (uint32_t)(((nt2 * 16 + kn_off) * ARS + kt * 16 + kk_off) * 2);
                    uint32_t kh4[4], kl4[4];
                    ldsm4(kh4, khu + boff);
                    ldsm4(kl4, klu + boff);
                    const int nt = nt2 * 2;
                    mma16816(sc[nt],     qh[kt], kh4);
                    mma16816(sc[nt],     qh[kt], kl4);
                    mma16816(sc[nt],     ql[kt], kh4);
                    mma16816(sc[nt + 1], qh[kt], kh4 + 2);
                    mma16816(sc[nt + 1], qh[kt], kl4 + 2);
                    mma16816(sc[nt + 1], ql[kt], kh4 + 2);
                }
            }

            // ---- scale + causal mask ----
            const bool needMask = (k0 + 64 > q0 + wrow);
#pragma unroll
            for (int nt = 0; nt < 8; ++nt) {
                const int c0g = k0 + nt * 8 + c2;
                sc[nt][0] *= scale; sc[nt][1] *= scale;
                sc[nt][2] *= scale; sc[nt][3] *= scale;
                if (needMask) {
                    if (c0g     > r0g) sc[nt][0] = -1e30f;
                    if (c0g + 1 > r0g) sc[nt][1] = -1e30f;
                    if (c0g     > r1g) sc[nt][2] = -1e30f;
                    if (c0g + 1 > r1g) sc[nt][3] = -1e30f;
                }
            }

            // ---- online softmax ----
            float mx0 = -1e30f, mx1 = -1e30f;
#pragma unroll
            for (int nt = 0; nt < 8; ++nt) {
                mx0 = fmaxf(mx0, fmaxf(sc[nt][0], sc[nt][1]));
                mx1 = fmaxf(mx1, fmaxf(sc[nt][2], sc[nt][3]));
            }
            mx0 = fmaxf(mx0, __shfl_xor_sync(0xffffffffu, mx0, 1));
            mx0 = fmaxf(mx0, __shfl_xor_sync(0xffffffffu, mx0, 2));
            mx1 = fmaxf(mx1, __shfl_xor_sync(0xffffffffu, mx1, 1));
            mx1 = fmaxf(mx1, __shfl_xor_sync(0xffffffffu, mx1, 2));

            const float mn0 = fmaxf(m0, mx0);
            const float mn1 = fmaxf(m1, mx1);
            const float corr0 = __expf(m0 - mn0);
            const float corr1 = __expf(m1 - mn1);
            m0 = mn0; m1 = mn1;

            float rs0 = 0.0f, rs1 = 0.0f;
#pragma unroll
            for (int nt = 0; nt < 8; ++nt) {
                float p0 = __expf(sc[nt][0] - mn0);
                float p1 = __expf(sc[nt][1] - mn0);
                float p2 = __expf(sc[nt][2] - mn1);
                float p3 = __expf(sc[nt][3] - mn1);
                sc[nt][0] = p0; sc[nt][1] = p1; sc[nt][2] = p2; sc[nt][3] = p3;
                rs0 += p0 + p1;
                rs1 += p2 + p3;
            }
            rs0 += __shfl_xor_sync(0xffffffffu, rs0, 1);
            rs0 += __shfl_xor_sync(0xffffffffu, rs0, 2);
            rs1 += __shfl_xor_sync(0xffffffffu, rs1, 1);
            rs1 += __shfl_xor_sync(0xffffffffu, rs1, 2);
            l0 = l0 * corr0 + rs0;
            l1 = l1 * corr1 + rs1;

#pragma unroll
            for (int nt = 0; nt < 8; ++nt) {
                oacc[nt][0] *= corr0; oacc[nt][1] *= corr0;
                oacc[nt][2] *= corr1; oacc[nt][3] *= corr1;
            }

            // ---- pack P (split hi/lo) ----
            uint32_t ph[4][4], pl[4][4];
#pragma unroll
            for (int kt = 0; kt < 4; ++kt) {
                const int t0 = 2 * kt, t1 = 2 * kt + 1;
                split2(sc[t0][0], sc[t0][1], ph[kt][0], pl[kt][0]);
                split2(sc[t0][2], sc[t0][3], ph[kt][1], pl[kt][1]);
                split2(sc[t1][0], sc[t1][1], ph[kt][2], pl[kt][2]);
                split2(sc[t1][2], sc[t1][3], ph[kt][3], pl[kt][3]);
            }

            // ---- O += P V ----
#pragma unroll
            for (int kt = 0; kt < 4; ++kt) {
#pragma unroll
                for (int nt2 = 0; nt2 < 4; ++nt2) {
                    const uint32_t boff =
                        (uint32_t)(((kt * 16 + vr_off) * ARS + nt2 * 16 + vc_off) * 2);
                    uint32_t vh4[4], vl4[4];
                    ldsm4t(vh4, vhu + boff);
                    ldsm4t(vl4, vlu + boff);
                    const int nt = nt2 * 2;
                    mma16816(oacc[nt],     ph[kt], vh4);
                    mma16816(oacc[nt],     ph[kt], vl4);
                    mma16816(oacc[nt],     pl[kt], vh4);
                    mma16816(oacc[nt + 1], ph[kt], vh4 + 2);
                    mma16816(oacc[nt + 1], ph[kt], vl4 + 2);
                    mma16816(oacc[nt + 1], pl[kt], vh4 + 2);
                }
            }
        }
        __syncthreads();
    }

    // ---- epilogue: normalize, split, write pre-split [B,S,D] ----
    const float inv0 = 1.0f / l0;
    const float inv1 = 1.0f / l1;
#pragma unroll
    for (int nt = 0; nt < 8; ++nt) {
        const int d = h * DH_ + nt * 8 + c2;
        uint32_t hh, ll;
        split2(oacc[nt][0] * inv0, oacc[nt][1] * inv0, hh, ll);
        *(uint32_t*)&AOh[(size_t)(b * S_ + r0g) * D_ + d] = hh;
        *(uint32_t*)&AOl[(size_t)(b * S_ + r0g) * D_ + d] = ll;
        split2(oacc[nt][2] * inv1, oacc[nt][3] * inv1, hh, ll);
        *(uint32_t*)&AOh[(size_t)(b * S_ + r1g) * D_ + d] = hh;
        *(uint32_t*)&AOl[(size_t)(b * S_ + r1g) * D_ + d] = ll;
    }
}

// ---------------------------------------------------------------------------
// Launch
// ---------------------------------------------------------------------------
extern "C" void kernel_launch(void* const* d_in, const int* in_sizes, int n_in,
                              void* d_out, int out_size)
{
    const float* x  = (const float*)d_in[0];
    const float* w[4] = {(const float*)d_in[1], (const float*)d_in[2],
                         (const float*)d_in[3], (const float*)d_in[4]};
    float* out = (float*)d_out;

    void *pxh, *pxl, *pwh, *pwl, *pqkvh, *pqkvl, *paoh, *paol;
    cudaGetSymbolAddress(&pxh, g_xh);     cudaGetSymbolAddress(&pxl, g_xl);
    cudaGetSymbolAddress(&pwh, g_wh);     cudaGetSymbolAddress(&pwl, g_wl);
    cudaGetSymbolAddress(&pqkvh, g_qkvh); cudaGetSymbolAddress(&pqkvl, g_qkvl);
    cudaGetSymbolAddress(&paoh, g_aoh);   cudaGetSymbolAddress(&paol, g_aol);

    __nv_bfloat16* xh = (__nv_bfloat16*)pxh;     __nv_bfloat16* xl = (__nv_bfloat16*)pxl;
    __nv_bfloat16* wh = (__nv_bfloat16*)pwh;     __nv_bfloat16* wl = (__nv_bfloat16*)pwl;
    __nv_bfloat16* qkvh = (__nv_bfloat16*)pqkvh; __nv_bfloat16* qkvl = (__nv_bfloat16*)pqkvl;
    __nv_bfloat16* aoh = (__nv_bfloat16*)paoh;   __nv_bfloat16* aol = (__nv_bfloat16*)paol;

    // Pre-split x and weights
    {
        const int n4x = M_ * D_ / 4;
        split_fp32<<<(n4x + 255) / 256, 256>>>((const float4*)x, (uint2*)xh, (uint2*)xl, n4x);
        const int n4w = D_ * D_ / 4;
        for (int i = 0; i < 4; ++i)
            split_fp32<<<(n4w + 255) / 256, 256>>>((const float4*)w[i],
                (uint2*)(wh + (size_t)i * D_ * D_), (uint2*)(wl + (size_t)i * D_ * D_), n4w);
    }

    cudaFuncSetAttribute(gemm_bf16<0>, cudaFuncAttributeMaxDynamicSharedMemorySize, GEMM_SMEM);
    cudaFuncSetAttribute(gemm_bf16<1>, cudaFuncAttributeMaxDynamicSharedMemorySize, GEMM_SMEM);
    cudaFuncSetAttribute(attn_mma,     cudaFuncAttributeMaxDynamicSharedMemorySize, ATT_SMEM);

    // Fused QKV: grid.x = 3 weights x 8 n-tiles
    dim3 qkv_grid(24, M_ / 128);
    gemm_bf16<0><<<qkv_grid, 256, GEMM_SMEM>>>(xh, xl, wh, wl, qkvh, qkvl, nullptr);

    dim3 attn_grid(S_ / 128, H_, B_);     // (16, 16, 2)
    attn_mma<<<attn_grid, 256, ATT_SMEM>>>(
        qkvh + 0 * (size_t)M_ * D_, qkvl + 0 * (size_t)M_ * D_,
        qkvh + 1 * (size_t)M_ * D_, qkvl + 1 * (size_t)M_ * D_,
        qkvh + 2 * (size_t)M_ * D_, qkvl + 2 * (size_t)M_ * D_,
        aoh, aol);

    dim3 gemm_grid(D_ / 128, M_ / 128);   // (8, 32)
    gemm_bf16<1><<<gemm_grid, 256, GEMM_SMEM>>>(
        aoh, aol, wh + 3 * (size_t)D_ * D_, wl + 3 * (size_t)D_ * D_,
        nullptr, nullptr, out);
}

// round 8
// speedup vs baseline: 1.3248x; 1.0186x over previous
#include <cuda_runtime.h>
#include <cuda_bf16.h>
#include <cstdint>
#include <cstddef>

// ---------------------------------------------------------------------------
// Problem constants
// ---------------------------------------------------------------------------
constexpr int B_  = 2;
constexpr int S_  = 2048;
constexpr int D_  = 1024;
constexpr int H_  = 16;
constexpr int DH_ = 64;
constexpr int M_  = B_ * S_;   // 4096

// ---------------------------------------------------------------------------
// Scratch: pre-split bf16 hi/lo pairs (16B-aligned for cp.async)
// ---------------------------------------------------------------------------
__device__ __align__(256) __nv_bfloat16 g_xh[(size_t)M_ * D_], g_xl[(size_t)M_ * D_];
__device__ __align__(256) __nv_bfloat16 g_wh[4][(size_t)D_ * D_], g_wl[4][(size_t)D_ * D_];
__device__ __align__(256) __nv_bfloat16 g_qkvh[3][(size_t)M_ * D_], g_qkvl[3][(size_t)M_ * D_];
__device__ __align__(256) __nv_bfloat16 g_aoh[(size_t)M_ * D_], g_aol[(size_t)M_ * D_];

// ---------------------------------------------------------------------------
// Helpers
// ---------------------------------------------------------------------------
__device__ __forceinline__ void mma16816(float* c, const uint32_t* a, const uint32_t* b) {
    asm volatile(
        "mma.sync.aligned.m16n8k16.row.col.f32.bf16.bf16.f32 "
        "{%0,%1,%2,%3}, {%4,%5,%6,%7}, {%8,%9}, {%0,%1,%2,%3};"
        : "+f"(c[0]), "+f"(c[1]), "+f"(c[2]), "+f"(c[3])
        : "r"(a[0]), "r"(a[1]), "r"(a[2]), "r"(a[3]), "r"(b[0]), "r"(b[1]));
}

__device__ __forceinline__ void split2(float x, float y, uint32_t& hi, uint32_t& lo) {
    __nv_bfloat162 h = __floats2bfloat162_rn(x, y);
    float rx = x - __bfloat162float(h.x);
    float ry = y - __bfloat162float(h.y);
    __nv_bfloat162 l = __floats2bfloat162_rn(rx, ry);
    hi = *reinterpret_cast<uint32_t*>(&h);
    lo = *reinterpret_cast<uint32_t*>(&l);
}

__device__ __forceinline__ uint32_t smem_u32(const void* p) {
    uint32_t a;
    asm("{ .reg .u64 t; cvta.to.shared.u64 t, %1; cvt.u32.u64 %0, t; }" : "=r"(a) : "l"(p));
    return a;
}

__device__ __forceinline__ void ldsm4(uint32_t* r, uint32_t addr) {
    asm volatile("ldmatrix.sync.aligned.m8n8.x4.shared.b16 {%0,%1,%2,%3}, [%4];"
        : "=r"(r[0]), "=r"(r[1]), "=r"(r[2]), "=r"(r[3]) : "r"(addr));
}
__device__ __forceinline__ void ldsm4t(uint32_t* r, uint32_t addr) {
    asm volatile("ldmatrix.sync.aligned.m8n8.x4.trans.shared.b16 {%0,%1,%2,%3}, [%4];"
        : "=r"(r[0]), "=r"(r[1]), "=r"(r[2]), "=r"(r[3]) : "r"(addr));
}

__device__ __forceinline__ void cp16(uint32_t saddr, const void* g) {
    asm volatile("cp.async.cg.shared.global [%0], [%1], 16;" :: "r"(saddr), "l"(g));
}
__device__ __forceinline__ void cp_commit() { asm volatile("cp.async.commit_group;"); }
template <int N> __device__ __forceinline__ void cp_wait() {
    asm volatile("cp.async.wait_group %0;" :: "n"(N));
}

// ---------------------------------------------------------------------------
// Fused fp32 -> bf16 hi/lo splitter: x (1M float4) + 4 weights (256K each).
// ---------------------------------------------------------------------------
__global__ void split_all(const float4* __restrict__ x,
                          const float4* __restrict__ w0, const float4* __restrict__ w1,
                          const float4* __restrict__ w2, const float4* __restrict__ w3,
                          uint2* __restrict__ xh, uint2* __restrict__ xl,
                          uint2* __restrict__ wh, uint2* __restrict__ wl)
{
    const int i = blockIdx.x * blockDim.x + threadIdx.x;   // 0 .. 2M-1
    constexpr int NX = M_ * D_ / 4;        // 1,048,576
    constexpr int NW = D_ * D_ / 4;        // 262,144

    const float4* src;
    uint2 *dh, *dl;
    if (i < NX) {
        src = x + i; dh = xh + i; dl = xl + i;
    } else {
        const int j = i - NX;
        const int wsel = j / NW;           // 0..3
        const int k = j - wsel * NW;
        const float4* ws[4] = {w0, w1, w2, w3};
        src = ws[wsel] + k;
        dh = wh + (size_t)wsel * NW + k;
        dl = wl + (size_t)wsel * NW + k;
    }
    float4 f = *src;
    uint32_t h01, l01, h23, l23;
    split2(f.x, f.y, h01, l01);
    split2(f.z, f.w, h23, l23);
    *dh = make_uint2(h01, h23);
    *dl = make_uint2(l01, l23);
}

// ---------------------------------------------------------------------------
// GEMM on pre-split bf16, cp.async 2-stage pipeline, ONE barrier per k-iter.
// out = A * W^T, 3-term split. Tile 128x128xK32, 8 warps, warp 64x32.
// MODE 0: fused QKV (blockIdx.x>>3 selects weight), scatter bf16 hi/lo.
// MODE 1: single weight, fp32 row-major output.
// ---------------------------------------------------------------------------
constexpr int RS = 40;                                   // 32 data + 8 pad
constexpr int GEMM_TILE_BF16 = 128 * RS;
constexpr int GEMM_SMEM = 2 * 4 * GEMM_TILE_BF16 * 2;    // 81920 B

template <int MODE>
__global__ __launch_bounds__(256, 2)
void gemm_bf16(const __nv_bfloat16* __restrict__ Ah_g, const __nv_bfloat16* __restrict__ Al_g,
               const __nv_bfloat16* __restrict__ Wh0, const __nv_bfloat16* __restrict__ Wl0,
               __nv_bfloat16* __restrict__ Oh0, __nv_bfloat16* __restrict__ Ol0,
               float* __restrict__ Of)
{
    extern __shared__ __nv_bfloat16 smem[];

    const int tid  = threadIdx.x;
    const int wid  = tid >> 5;
    const int lane = tid & 31;
    const int wm   = wid >> 2;
    const int wn   = wid & 3;
    const int lq   = lane >> 2;
    const int lr   = (lane & 3) << 1;

    int wsel, bn;
    if (MODE == 0) { wsel = blockIdx.x >> 3; bn = (blockIdx.x & 7) * 128; }
    else           { wsel = 0;               bn = blockIdx.x * 128; }
    const int bm = blockIdx.y * 128;

    const __nv_bfloat16* Bh_g = Wh0 + (size_t)wsel * D_ * D_;
    const __nv_bfloat16* Bl_g = Wl0 + (size_t)wsel * D_ * D_;

    const uint32_t sbase = smem_u32(smem);

    auto issue = [&](int k0, int s) {
#pragma unroll
        for (int i = 0; i < 8; ++i) {
            const int a    = i >> 1;
            const int c    = (i & 1) * 256 + tid;
            const int row  = c >> 2;
            const int c16  = c & 3;
            const size_t go = (size_t)((a < 2 ? bm : bn) + row) * D_ + k0 + c16 * 8;
            const __nv_bfloat16* g =
                (a == 0) ? Ah_g + go : (a == 1) ? Al_g + go :
                (a == 2) ? Bh_g + go : Bl_g + go;
            const uint32_t sa = sbase + (uint32_t)(((s * 4 + a) * GEMM_TILE_BF16
                                 + row * RS) * 2 + c16 * 16);
            cp16(sa, g);
        }
        cp_commit();
    };

    float acc[4][4][4];
#pragma unroll
    for (int i = 0; i < 4; i++)
#pragma unroll
        for (int j = 0; j < 4; j++)
#pragma unroll
            for (int r = 0; r < 4; r++) acc[i][j][r] = 0.0f;

    issue(0, 0);

    for (int kt = 0; kt < 32; ++kt) {
        const int s = kt & 1;
        cp_wait<0>();          // group kt complete (overlapped with compute kt-1)
        __syncthreads();       // publish tile kt; all warps done reading buf s^1
        if (kt < 31) issue((kt + 1) * 32, s ^ 1);

        const __nv_bfloat16* Ahs = smem + (s * 4 + 0) * GEMM_TILE_BF16;
        const __nv_bfloat16* Als = smem + (s * 4 + 1) * GEMM_TILE_BF16;
        const __nv_bfloat16* Bhs = smem + (s * 4 + 2) * GEMM_TILE_BF16;
        const __nv_bfloat16* Bls = smem + (s * 4 + 3) * GEMM_TILE_BF16;

#pragma unroll
        for (int ks = 0; ks < 2; ++ks) {
            const int kb = ks * 16 + lr;

            uint32_t bh[4][2], bl[4][2];
#pragma unroll
            for (int nt = 0; nt < 4; ++nt) {
                const int n = wn * 32 + nt * 8 + lq;
                bh[nt][0] = *(const uint32_t*)&Bhs[n * RS + kb];
                bh[nt][1] = *(const uint32_t*)&Bhs[n * RS + kb + 8];
                bl[nt][0] = *(const uint32_t*)&Bls[n * RS + kb];
                bl[nt][1] = *(const uint32_t*)&Bls[n * RS + kb + 8];
            }

#pragma unroll
            for (int mt = 0; mt < 4; ++mt) {
                const int r = wm * 64 + mt * 16 + lq;
                uint32_t ah[4], al[4];
                ah[0] = *(const uint32_t*)&Ahs[r * RS + kb];
                ah[1] = *(const uint32_t*)&Ahs[(r + 8) * RS + kb];
                ah[2] = *(const uint32_t*)&Ahs[r * RS + kb + 8];
                ah[3] = *(const uint32_t*)&Ahs[(r + 8) * RS + kb + 8];
                al[0] = *(const uint32_t*)&Als[r * RS + kb];
                al[1] = *(const uint32_t*)&Als[(r + 8) * RS + kb];
                al[2] = *(const uint32_t*)&Als[r * RS + kb + 8];
                al[3] = *(const uint32_t*)&Als[(r + 8) * RS + kb + 8];
#pragma unroll
                for (int nt = 0; nt < 4; ++nt) {
                    mma16816(acc[mt][nt], ah, bh[nt]);
                    mma16816(acc[mt][nt], ah, bl[nt]);
                    mma16816(acc[mt][nt], al, bh[nt]);
                }
            }
        }
    }

    __nv_bfloat16* Oh = (MODE == 0) ? Oh0 + (size_t)wsel * M_ * D_ : nullptr;
    __nv_bfloat16* Ol = (MODE == 0) ? Ol0 + (size_t)wsel * M_ * D_ : nullptr;

#pragma unroll
    for (int mt = 0; mt < 4; ++mt) {
#pragma unroll
        for (int nt = 0; nt < 4; ++nt) {
            const int n  = bn + wn * 32 + nt * 8 + lr;
            const int m0 = bm + wm * 64 + mt * 16 + lq;
#pragma unroll
            for (int half = 0; half < 2; ++half) {
                const int m = m0 + half * 8;
                const float v0 = acc[mt][nt][half * 2];
                const float v1 = acc[mt][nt][half * 2 + 1];
                if (MODE == 0) {
                    const int b_ = m >> 11;
                    const int s_ = m & 2047;
                    const int h_ = n >> 6;
                    const int d_ = n & 63;
                    const size_t off = (((size_t)(b_ * H_ + h_) * S_ + s_) << 6) + d_;
                    uint32_t hh, ll;
                    split2(v0, v1, hh, ll);
                    *(uint32_t*)&Oh[off] = hh;
                    *(uint32_t*)&Ol[off] = ll;
                } else {
                    *(float2*)&Of[(size_t)m * D_ + n] = make_float2(v0, v1);
                }
            }
        }
    }
}

// ---------------------------------------------------------------------------
// Flash attention, cp.async 3-stage K/V pipeline, ONE barrier per tile.
// Block = 128 q rows x (head, batch). 8 warps x 16 rows.
// smem: [stage 3][array 4: Kh,Kl,Vh,Vl][64*ARS], ARS=72. 110592 B dynamic.
// ---------------------------------------------------------------------------
constexpr int ARS = 72;                       // 64 data + 8 pad
constexpr int ATT_TILE_BF16 = 64 * ARS;       // 4608
constexpr int ATT_SMEM = 3 * 4 * ATT_TILE_BF16 * 2;   // 110592 B

__global__ __launch_bounds__(256)
void attn_mma(const __nv_bfloat16* __restrict__ Qh_g, const __nv_bfloat16* __restrict__ Ql_g,
              const __nv_bfloat16* __restrict__ Kh_g, const __nv_bfloat16* __restrict__ Kl_g,
              const __nv_bfloat16* __restrict__ Vh_g, const __nv_bfloat16* __restrict__ Vl_g,
              __nv_bfloat16* __restrict__ AOh, __nv_bfloat16* __restrict__ AOl)
{
    extern __shared__ __nv_bfloat16 asmem[];

    const int tid  = threadIdx.x;
    const int wid  = tid >> 5;
    const int lane = tid & 31;
    const int lq   = lane >> 2;
    const int c2   = (lane & 3) << 1;

    const int qt = (int)gridDim.x - 1 - (int)blockIdx.x;   // heavy tiles first
    const int q0 = qt * 128;
    const int h  = blockIdx.y;
    const int b  = blockIdx.z;
    const size_t base = (size_t)(b * H_ + h) * S_ * DH_;
    const int wrow = wid * 16;

    const uint32_t sbase = smem_u32(asmem);
    const int kn_off = (lane & 7) + ((lane & 16) ? 8 : 0);
    const int kk_off = (lane & 8);
    const int vr_off = lane & 15;
    const int vc_off = (lane & 16) ? 8 : 0;

    auto issue = [&](int k0, int s) {
#pragma unroll
        for (int it = 0; it < 2; ++it) {
            const int idx = tid + it * 256;
            const int row = idx >> 3;
            const int c16 = idx & 7;
            const size_t go = base + (size_t)(k0 + row) * DH_ + c16 * 8;
            const uint32_t so = (uint32_t)(row * ARS * 2 + c16 * 16);
#pragma unroll
            for (int a = 0; a < 4; ++a) {
                const __nv_bfloat16* g =
                    (a == 0) ? Kh_g + go : (a == 1) ? Kl_g + go :
                    (a == 2) ? Vh_g + go : Vl_g + go;
                cp16(sbase + (uint32_t)((s * 4 + a) * ATT_TILE_BF16 * 2) + so, g);
            }
        }
        cp_commit();
    };

    // ---- Q fragments ----
    uint32_t qh[4][4], ql[4][4];
    {
        const __nv_bfloat16* qhp = Qh_g + base + (size_t)(q0 + wrow + lq) * DH_;
        const __nv_bfloat16* qlp = Ql_g + base + (size_t)(q0 + wrow + lq) * DH_;
#pragma unroll
        for (int kt = 0; kt < 4; ++kt) {
            const int c = kt * 16 + c2;
            qh[kt][0] = *(const uint32_t*)(qhp + c);
            qh[kt][1] = *(const uint32_t*)(qhp + 8 * DH_ + c);
            qh[kt][2] = *(const uint32_t*)(qhp + c + 8);
            qh[kt][3] = *(const uint32_t*)(qhp + 8 * DH_ + c + 8);
            ql[kt][0] = *(const uint32_t*)(qlp + c);
            ql[kt][1] = *(const uint32_t*)(qlp + 8 * DH_ + c);
            ql[kt][2] = *(const uint32_t*)(qlp + c + 8);
            ql[kt][3] = *(const uint32_t*)(qlp + 8 * DH_ + c + 8);
        }
    }

    float oacc[8][4];
#pragma unroll
    for (int nt = 0; nt < 8; ++nt)
#pragma unroll
        for (int r = 0; r < 4; ++r) oacc[nt][r] = 0.0f;

    float m0 = -1e30f, m1 = -1e30f, l0 = 0.0f, l1 = 0.0f;

    constexpr float scale = 0.125f;
    const int r0g = q0 + wrow + lq;
    const int r1g = r0g + 8;
    const int rmaxWarp = q0 + wrow + 15;
    const int ntiles = q0 / 64 + 2;   // >= 2

    issue(0, 0);
    issue(64, 1);

    for (int t = 0; t < ntiles; ++t) {
        const int s  = t % 3;
        const int k0 = t * 64;
        if (t + 1 < ntiles) cp_wait<1>();   // group t done (t+1 may fly)
        else                cp_wait<0>();   // last: everything done
        __syncthreads();                    // publish tile t; stage (t+2)%3 free
        if (t + 2 < ntiles) issue((t + 2) * 64, (t + 2) % 3);

        if (k0 <= rmaxWarp) {
            const uint32_t khu = sbase + (uint32_t)((s * 4 + 0) * ATT_TILE_BF16 * 2);
            const uint32_t klu = sbase + (uint32_t)((s * 4 + 1) * ATT_TILE_BF16 * 2);
            const uint32_t vhu = sbase + (uint32_t)((s * 4 + 2) * ATT_TILE_BF16 * 2);
            const uint32_t vlu = sbase + (uint32_t)((s * 4 + 3) * ATT_TILE_BF16 * 2);

            // ---- S = Q K^T ----
            float sc[8][4];
#pragma unroll
            for (int nt = 0; nt < 8; ++nt)
#pragma unroll
                for (int r = 0; r < 4; ++r) sc[nt][r] = 0.0f;

#pragma unroll
            for (int kt = 0; kt < 4; ++kt) {
#pragma unroll
                for (int nt2 = 0; nt2 < 4; ++nt2) {
                    const uint32_t boff =
                        (uint32_t)(((nt2 * 16 + kn_off) * ARS + kt * 16 + kk_off) * 2);
                    uint32_t kh4[4], kl4[4];
                    ldsm4(kh4, khu + boff);
                    ldsm4(kl4, klu + boff);
                    const int nt = nt2 * 2;
                    mma16816(sc[nt],     qh[kt], kh4);
                    mma16816(sc[nt],     qh[kt], kl4);
                    mma16816(sc[nt],     ql[kt], kh4);
                    mma16816(sc[nt + 1], qh[kt], kh4 + 2);
                    mma16816(sc[nt + 1], qh[kt], kl4 + 2);
                    mma16816(sc[nt + 1], ql[kt], kh4 + 2);
                }
            }

            // ---- scale + causal mask ----
            const bool needMask = (k0 + 64 > q0 + wrow);
#pragma unroll
            for (int nt = 0; nt < 8; ++nt) {
                const int c0g = k0 + nt * 8 + c2;
                sc[nt][0] *= scale; sc[nt][1] *= scale;
                sc[nt][2] *= scale; sc[nt][3] *= scale;
                if (needMask) {
                    if (c0g     > r0g) sc[nt][0] = -1e30f;
                    if (c0g + 1 > r0g) sc[nt][1] = -1e30f;
                    if (c0g     > r1g) sc[nt][2] = -1e30f;
                    if (c0g + 1 > r1g) sc[nt][3] = -1e30f;
                }
            }

            // ---- online softmax ----
            float mx0 = -1e30f, mx1 = -1e30f;
#pragma unroll
            for (int nt = 0; nt < 8; ++nt) {
                mx0 = fmaxf(mx0, fmaxf(sc[nt][0], sc[nt][1]));
                mx1 = fmaxf(mx1, fmaxf(sc[nt][2], sc[nt][3]));
            }
            mx0 = fmaxf(mx0, __shfl_xor_sync(0xffffffffu, mx0, 1));
            mx0 = fmaxf(mx0, __shfl_xor_sync(0xffffffffu, mx0, 2));
            mx1 = fmaxf(mx1, __shfl_xor_sync(0xffffffffu, mx1, 1));
            mx1 = fmaxf(mx1, __shfl_xor_sync(0xffffffffu, mx1, 2));

            const float mn0 = fmaxf(m0, mx0);
            const float mn1 = fmaxf(m1, mx1);
            const float corr0 = __expf(m0 - mn0);
            const float corr1 = __expf(m1 - mn1);
            m0 = mn0; m1 = mn1;

            float rs0 = 0.0f, rs1 = 0.0f;
#pragma unroll
            for (int nt = 0; nt < 8; ++nt) {
                float p0 = __expf(sc[nt][0] - mn0);
                float p1 = __expf(sc[nt][1] - mn0);
                float p2 = __expf(sc[nt][2] - mn1);
                float p3 = __expf(sc[nt][3] - mn1);
                sc[nt][0] = p0; sc[nt][1] = p1; sc[nt][2] = p2; sc[nt][3] = p3;
                rs0 += p0 + p1;
                rs1 += p2 + p3;
            }
            rs0 += __shfl_xor_sync(0xffffffffu, rs0, 1);
            rs0 += __shfl_xor_sync(0xffffffffu, rs0, 2);
            rs1 += __shfl_xor_sync(0xffffffffu, rs1, 1);
            rs1 += __shfl_xor_sync(0xffffffffu, rs1, 2);
            l0 = l0 * corr0 + rs0;
            l1 = l1 * corr1 + rs1;

#pragma unroll
            for (int nt = 0; nt < 8; ++nt) {
                oacc[nt][0] *= corr0; oacc[nt][1] *= corr0;
                oacc[nt][2] *= corr1; oacc[nt][3] *= corr1;
            }

            // ---- pack P (split hi/lo) ----
            uint32_t ph[4][4], pl[4][4];
#pragma unroll
            for (int kt = 0; kt < 4; ++kt) {
                const int t0 = 2 * kt, t1 = 2 * kt + 1;
                split2(sc[t0][0], sc[t0][1], ph[kt][0], pl[kt][0]);
                split2(sc[t0][2], sc[t0][3], ph[kt][1], pl[kt][1]);
                split2(sc[t1][0], sc[t1][1], ph[kt][2], pl[kt][2]);
                split2(sc[t1][2], sc[t1][3], ph[kt][3], pl[kt][3]);
            }

            // ---- O += P V ----
#pragma unroll
            for (int kt = 0; kt < 4; ++kt) {
#pragma unroll
                for (int nt2 = 0; nt2 < 4; ++nt2) {
                    const uint32_t boff =
                        (uint32_t)(((kt * 16 + vr_off) * ARS + nt2 * 16 + vc_off) * 2);
                    uint32_t vh4[4], vl4[4];
                    ldsm4t(vh4, vhu + boff);
                    ldsm4t(vl4, vlu + boff);
                    const int nt = nt2 * 2;
                    mma16816(oacc[nt],     ph[kt], vh4);
                    mma16816(oacc[nt],     ph[kt], vl4);
                    mma16816(oacc[nt],     pl[kt], vh4);
                    mma16816(oacc[nt + 1], ph[kt], vh4 + 2);
                    mma16816(oacc[nt + 1], ph[kt], vl4 + 2);
                    mma16816(oacc[nt + 1], pl[kt], vh4 + 2);
                }
            }
        }
    }

    // ---- epilogue: normalize, split, write pre-split [B,S,D] ----
    const float inv0 = 1.0f / l0;
    const float inv1 = 1.0f / l1;
#pragma unroll
    for (int nt = 0; nt < 8; ++nt) {
        const int d = h * DH_ + nt * 8 + c2;
        uint32_t hh, ll;
        split2(oacc[nt][0] * inv0, oacc[nt][1] * inv0, hh, ll);
        *(uint32_t*)&AOh[(size_t)(b * S_ + r0g) * D_ + d] = hh;
        *(uint32_t*)&AOl[(size_t)(b * S_ + r0g) * D_ + d] = ll;
        split2(oacc[nt][2] * inv1, oacc[nt][3] * inv1, hh, ll);
        *(uint32_t*)&AOh[(size_t)(b * S_ + r1g) * D_ + d] = hh;
        *(uint32_t*)&AOl[(size_t)(b * S_ + r1g) * D_ + d] = ll;
    }
}

// ---------------------------------------------------------------------------
// Launch
// ---------------------------------------------------------------------------
extern "C" void kernel_launch(void* const* d_in, const int* in_sizes, int n_in,
                              void* d_out, int out_size)
{
    const float* x  = (const float*)d_in[0];
    const float* w0 = (const float*)d_in[1];
    const float* w1 = (const float*)d_in[2];
    const float* w2 = (const float*)d_in[3];
    const float* w3 = (const float*)d_in[4];
    float* out = (float*)d_out;

    void *pxh, *pxl, *pwh, *pwl, *pqkvh, *pqkvl, *paoh, *paol;
    cudaGetSymbolAddress(&pxh, g_xh);     cudaGetSymbolAddress(&pxl, g_xl);
    cudaGetSymbolAddress(&pwh, g_wh);     cudaGetSymbolAddress(&pwl, g_wl);
    cudaGetSymbolAddress(&pqkvh, g_qkvh); cudaGetSymbolAddress(&pqkvl, g_qkvl);
    cudaGetSymbolAddress(&paoh, g_aoh);   cudaGetSymbolAddress(&paol, g_aol);

    __nv_bfloat16* xh = (__nv_bfloat16*)pxh;     __nv_bfloat16* xl = (__nv_bfloat16*)pxl;
    __nv_bfloat16* wh = (__nv_bfloat16*)pwh;     __nv_bfloat16* wl = (__nv_bfloat16*)pwl;
    __nv_bfloat16* qkvh = (__nv_bfloat16*)pqkvh; __nv_bfloat16* qkvl = (__nv_bfloat16*)pqkvl;
    __nv_bfloat16* aoh = (__nv_bfloat16*)paoh;   __nv_bfloat16* aol = (__nv_bfloat16*)paol;

    // Pre-split x + all weights in one launch (2M float4s)
    {
        const int ntot = M_ * D_ / 4 + 4 * (D_ * D_ / 4);
        split_all<<<(ntot + 255) / 256, 256>>>(
            (const float4*)x, (const float4*)w0, (const float4*)w1,
            (const float4*)w2, (const float4*)w3,
            (uint2*)xh, (uint2*)xl, (uint2*)wh, (uint2*)wl);
    }

    cudaFuncSetAttribute(gemm_bf16<0>, cudaFuncAttributeMaxDynamicSharedMemorySize, GEMM_SMEM);
    cudaFuncSetAttribute(gemm_bf16<1>, cudaFuncAttributeMaxDynamicSharedMemorySize, GEMM_SMEM);
    cudaFuncSetAttribute(attn_mma,     cudaFuncAttributeMaxDynamicSharedMemorySize, ATT_SMEM);

    // Fused QKV: grid.x = 3 weights x 8 n-tiles
    dim3 qkv_grid(24, M_ / 128);
    gemm_bf16<0><<<qkv_grid, 256, GEMM_SMEM>>>(xh, xl, wh, wl, qkvh, qkvl, nullptr);

    dim3 attn_grid(S_ / 128, H_, B_);     // (16, 16, 2)
    attn_mma<<<attn_grid, 256, ATT_SMEM>>>(
        qkvh + 0 * (size_t)M_ * D_, qkvl + 0 * (size_t)M_ * D_,
        qkvh + 1 * (size_t)M_ * D_, qkvl + 1 * (size_t)M_ * D_,
        qkvh + 2 * (size_t)M_ * D_, qkvl + 2 * (size_t)M_ * D_,
        aoh, aol);

    dim3 gemm_grid(D_ / 128, M_ / 128);   // (8, 32)
    gemm_bf16<1><<<gemm_grid, 256, GEMM_SMEM>>>(
        aoh, aol, wh + 3 * (size_t)D_ * D_, wl + 3 * (size_t)D_ * D_,
        nullptr, nullptr, out);
}